// round 12
// baseline (speedup 1.0000x reference)
#include <cuda_runtime.h>
#include <cstddef>

#define B_  16
#define C_  1024
#define T_  16
#define HW_ 360      // H*W = 12*30
#define K_  120
#define ROWS_ 482    // 1 + 120 + 1 + 360
#define CHUNKS 32    // 32 channels per chunk (scores role)
#define STRIDE_T (T_*HW_)   // 5760 floats between consecutive c for fixed (b,t,p)

// Scratch (no allocations allowed in kernel_launch)
__device__ float4 g_partial4[B_][CHUNKS][HW_/4];   // [b][chunk][90] float4 == 360 floats
__device__ int    g_topk[B_][K_];

// ---------------------------------------------------------------------------
// Kernel A: fused scores + t1copy. grid (32+96, B), block 384.
//  blockIdx.x < 32  : scores role — partial dot products for chunk=blockIdx.x.
//  blockIdx.x >= 32 : t1copy role — transpose one 128ch x 32p tile of the
//                     t=1 slice into out rows 122..481.
// The two roles are independent; fusing overlaps their DRAM streams.
// Shared memory is a 16.5KB union (scores: cls+red; t1copy: tile[32][129]).
// ---------------------------------------------------------------------------
__global__ void __launch_bounds__(384, 2)
fusedA_kernel(const float* __restrict__ x,
              const float* __restrict__ cls,
              float* __restrict__ out) {
    __shared__ __align__(16) float sm[32 * 129];    // 16512 B
    const int b   = blockIdx.y;
    const int tid = threadIdx.x;

    if (blockIdx.x < CHUNKS) {
        // ================= scores role =================
        const int chunk = blockIdx.x;
        float*  cls_s = sm;                          // [32]
        float4* red   = (float4*)(sm + 32);          // [360], 16B-aligned

        if (tid < 32)
            cls_s[tid] = cls[(size_t)b * T_ * C_ + (size_t)chunk * 32 + tid];  // t=0
        __syncthreads();

        if (tid < 360) {
            const int p4 = tid % 90;
            const int cg = tid / 90;

            const float* base = x + ((size_t)(b * C_ + chunk * 32 + cg * 8)) * STRIDE_T + 4 * p4;

            float4 v[8];
#pragma unroll
            for (int j = 0; j < 8; ++j)
                v[j] = *(const float4*)(base + (size_t)j * STRIDE_T);

            float4 acc = make_float4(0.f, 0.f, 0.f, 0.f);
#pragma unroll
            for (int j = 0; j < 8; ++j) {
                const float w = cls_s[cg * 8 + j];
                acc.x = fmaf(w, v[j].x, acc.x);
                acc.y = fmaf(w, v[j].y, acc.y);
                acc.z = fmaf(w, v[j].z, acc.z);
                acc.w = fmaf(w, v[j].w, acc.w);
            }
            red[cg * 90 + p4] = acc;
        }
        __syncthreads();

        if (tid < 90) {
            const float4 a  = red[tid];
            const float4 b1 = red[90 + tid];
            const float4 c  = red[180 + tid];
            const float4 d  = red[270 + tid];
            float4 s;
            s.x = ((a.x + b1.x) + c.x) + d.x;
            s.y = ((a.y + b1.y) + c.y) + d.y;
            s.z = ((a.z + b1.z) + c.z) + d.z;
            s.w = ((a.w + b1.w) + c.w) + d.w;
            g_partial4[b][chunk][tid] = s;
        }
    } else {
        // ================= t1copy role =================
        const int r  = blockIdx.x - CHUNKS;          // 0..95
        const int ct = r / 12;                       // 0..7  (128 channels)
        const int pt = r % 12;                       // 0..11 (32 patches)
        const int c0 = ct * 128;
        const int p0 = pt * 32;

        float (*tile)[129] = (float(*)[129])sm;      // [32 p][128 c], pitch 129

        // load: float4 along p, scalar STS (banks (4p4+j+cl)%32 all distinct)
        for (int idx = tid; idx < 1024; idx += 384) {
            const int p4 = idx & 7;                  // float4 index along p
            const int cl = idx >> 3;                 // 0..127
            const float4 v = *(const float4*)&x[((size_t)(b * C_ + c0 + cl)) * STRIDE_T
                                                + HW_ + p0 + 4 * p4];
            tile[4 * p4 + 0][cl] = v.x;
            tile[4 * p4 + 1][cl] = v.y;
            tile[4 * p4 + 2][cl] = v.z;
            tile[4 * p4 + 3][cl] = v.w;
        }
        __syncthreads();

        // write: warp owns one p row, lanes sweep channels.
        // LDS banks (or+lane)%32 distinct; STG 4x128B coalesced.
        for (int idx = tid; idx < 1024; idx += 384) {
            const int orow_i = idx >> 5;             // 0..31 (constant per warp)
            const int lane   = idx & 31;
            const int pr = p0 + orow_i;
            if (pr < HW_) {
                float* orow = out + ((size_t)b * ROWS_ + 122 + pr) * C_ + c0;
#pragma unroll
                for (int q = 0; q < 4; ++q)
                    orow[lane + 32 * q] = tile[orow_i][lane + 32 * q];
            }
        }
    }
}

// ---------------------------------------------------------------------------
// K2: per-batch reduce (32 chunks, double, fixed order) + bitonic sort of 512
// with one element per thread (shfl for j<32: 35 of 45 phases barrier-free).
// Key order: value desc, index asc (jax.lax.top_k semantics).
// Also writes the two cls rows of the output. grid (B), 512 threads.
// ---------------------------------------------------------------------------
__global__ void topk_kernel(const float* __restrict__ cls,
                            float* __restrict__ out) {
    const int b   = blockIdx.x;
    const int tid = threadIdx.x;

    __shared__ double sv[512];
    __shared__ int    si[512];

    double v;
    int    idx = tid;
    if (tid < HW_) {
        const float* gp = (const float*)&g_partial4[b][0][0];
        double s = 0.0;
#pragma unroll 8
        for (int j = 0; j < CHUNKS; ++j) s += (double)gp[j * HW_ + tid];
        v = s;
    } else {
        v = -1e300;
    }

    for (int k = 2; k <= 512; k <<= 1) {
        const bool up = ((tid & k) == 0);
        int j = k >> 1;
        for (; j >= 32; j >>= 1) {
            sv[tid] = v; si[tid] = idx;
            __syncthreads();
            const double pv = sv[tid ^ j];
            const int    pi = si[tid ^ j];
            __syncthreads();
            const bool iLess = (v > pv) || (v == pv && idx < pi);
            const bool lower = ((tid & j) == 0);
            const bool keepOwn = lower ? (up ? iLess : !iLess)
                                       : (up ? !iLess : iLess);
            if (!keepOwn) { v = pv; idx = pi; }
        }
        for (; j >= 1; j >>= 1) {
            const double pv = __shfl_xor_sync(0xffffffffu, v, j);
            const int    pi = __shfl_xor_sync(0xffffffffu, idx, j);
            const bool iLess = (v > pv) || (v == pv && idx < pi);
            const bool lower = ((tid & j) == 0);
            const bool keepOwn = lower ? (up ? iLess : !iLess)
                                       : (up ? !iLess : iLess);
            if (!keepOwn) { v = pv; idx = pi; }
        }
    }

    if (tid < K_) g_topk[b][tid] = idx;

    // cls rows via float4: row 0 = cls[b,0,:], row 121 = cls[b,1,:]
    {
        const float4* c4 = (const float4*)(cls + (size_t)b * T_ * C_);
        float4* o4 = (float4*)(out + (size_t)b * ROWS_ * C_);
        if (tid < 256)
            o4[tid] = c4[tid];                            // row 0
        else
            o4[(size_t)121 * (C_ / 4) + (tid - 256)] = c4[(C_ / 4) + (tid - 256)]; // row 121
    }
}

// ---------------------------------------------------------------------------
// K3: gather of the 120 selected t=0 tokens.
// grid (16 ctiles of 64 ch, B), block (32,8).
// Tokens along lanes: each warp-LDG reads 32 token positions inside ONE
// 1440-byte channel row (<=12 lines, L1-cached across token groups). Reads
// are L2-resident (t=0 slice streamed by kernel A). smem pitch 65 ->
// conflict-free both phases. Writes coalesced.
// ---------------------------------------------------------------------------
__global__ void gather_kernel(const float* __restrict__ x,
                              float* __restrict__ out) {
    const int c0 = blockIdx.x * 64;
    const int b  = blockIdx.y;
    const int tx = threadIdx.x;          // 0..31
    const int ty = threadIdx.y;          // 0..7
    const int tid = ty * 32 + tx;

    __shared__ float g[120][65];
    __shared__ int   pidx[128];

    for (int i = tid; i < K_; i += 256)
        pidx[i] = g_topk[b][i];
    __syncthreads();

    // load phase: token groups of 32 along lanes, channels along ty+8*cg
#pragma unroll
    for (int tg = 0; tg < 4; ++tg) {
        const int tok = tg * 32 + tx;
        const bool valid = (tok < K_);
        const int p = valid ? pidx[tok] : 0;
#pragma unroll
        for (int cg = 0; cg < 8; ++cg) {
            const int c = ty + 8 * cg;   // 0..63
            if (valid)
                g[tok][c] = x[((size_t)(b * C_ + c0 + c)) * STRIDE_T + p]; // t=0
        }
    }
    __syncthreads();

    // write phase: warp ty owns tokens ty, ty+8, ... ; lanes sweep channels
    for (int tok = ty; tok < K_; tok += 8) {
        float* orow = out + ((size_t)b * ROWS_ + 1 + tok) * C_ + c0;
        orow[tx]      = g[tok][tx];
        orow[32 + tx] = g[tok][32 + tx];
    }
}

// ---------------------------------------------------------------------------
extern "C" void kernel_launch(void* const* d_in, const int* in_sizes, int n_in,
                              void* d_out, int out_size) {
    const float* x   = (const float*)d_in[0];
    const float* cls = (const float*)d_in[1];
    // Defensive: x is the huge tensor (94,371,840 elems), cls is 262,144.
    if (n_in >= 2 && in_sizes[0] < in_sizes[1]) {
        const float* tmp = x; x = cls; cls = tmp;
    }
    float* out = (float*)d_out;

    fusedA_kernel <<<dim3(CHUNKS + 96, B_), 384>>>(x, cls, out);
    topk_kernel   <<<B_, 512>>>(cls, out);
    gather_kernel <<<dim3(16, B_), dim3(32, 8)>>>(x, out);
}

// round 13
// speedup vs baseline: 1.0097x; 1.0097x over previous
#include <cuda_runtime.h>
#include <cstddef>

#define B_  16
#define C_  1024
#define T_  16
#define HW_ 360      // H*W = 12*30
#define K_  120
#define ROWS_ 482    // 1 + 120 + 1 + 360
#define CHUNKS 32    // 32 channels per chunk (scores role)
#define STRIDE_T (T_*HW_)   // 5760 floats between consecutive c for fixed (b,t,p)

// Scratch (no allocations allowed in kernel_launch)
__device__ float4 g_partial4[B_][CHUNKS][HW_/4];   // [b][chunk][90] float4 == 360 floats
__device__ int    g_topk_sorted[B_][K_];           // (p<<16)|rank, ascending in p

// ---------------------------------------------------------------------------
// Kernel A: fused scores + t1copy. grid (32+96, B), block 384.
//  blockIdx.x < 32  : scores role — partial dot products for chunk=blockIdx.x.
//  blockIdx.x >= 32 : t1copy role — transpose one 128ch x 32p tile of the
//                     t=1 slice into out rows 122..481.
// Shared memory is a 16.5KB union (scores: cls+red; t1copy: tile[32][129]).
// ---------------------------------------------------------------------------
__global__ void __launch_bounds__(384, 2)
fusedA_kernel(const float* __restrict__ x,
              const float* __restrict__ cls,
              float* __restrict__ out) {
    __shared__ __align__(16) float sm[32 * 129];    // 16512 B
    const int b   = blockIdx.y;
    const int tid = threadIdx.x;

    if (blockIdx.x < CHUNKS) {
        // ================= scores role =================
        const int chunk = blockIdx.x;
        float*  cls_s = sm;                          // [32]
        float4* red   = (float4*)(sm + 32);          // [360], 16B-aligned

        if (tid < 32)
            cls_s[tid] = cls[(size_t)b * T_ * C_ + (size_t)chunk * 32 + tid];  // t=0
        __syncthreads();

        if (tid < 360) {
            const int p4 = tid % 90;
            const int cg = tid / 90;

            const float* base = x + ((size_t)(b * C_ + chunk * 32 + cg * 8)) * STRIDE_T + 4 * p4;

            float4 v[8];
#pragma unroll
            for (int j = 0; j < 8; ++j)
                v[j] = *(const float4*)(base + (size_t)j * STRIDE_T);

            float4 acc = make_float4(0.f, 0.f, 0.f, 0.f);
#pragma unroll
            for (int j = 0; j < 8; ++j) {
                const float w = cls_s[cg * 8 + j];
                acc.x = fmaf(w, v[j].x, acc.x);
                acc.y = fmaf(w, v[j].y, acc.y);
                acc.z = fmaf(w, v[j].z, acc.z);
                acc.w = fmaf(w, v[j].w, acc.w);
            }
            red[cg * 90 + p4] = acc;
        }
        __syncthreads();

        if (tid < 90) {
            const float4 a  = red[tid];
            const float4 b1 = red[90 + tid];
            const float4 c  = red[180 + tid];
            const float4 d  = red[270 + tid];
            float4 s;
            s.x = ((a.x + b1.x) + c.x) + d.x;
            s.y = ((a.y + b1.y) + c.y) + d.y;
            s.z = ((a.z + b1.z) + c.z) + d.z;
            s.w = ((a.w + b1.w) + c.w) + d.w;
            g_partial4[b][chunk][tid] = s;
        }
    } else {
        // ================= t1copy role =================
        const int r  = blockIdx.x - CHUNKS;          // 0..95
        const int ct = r / 12;                       // 0..7  (128 channels)
        const int pt = r % 12;                       // 0..11 (32 patches)
        const int c0 = ct * 128;
        const int p0 = pt * 32;

        float (*tile)[129] = (float(*)[129])sm;      // [32 p][128 c], pitch 129

        // load: float4 along p, scalar STS (banks (4p4+j+cl)%32 all distinct)
        for (int idx = tid; idx < 1024; idx += 384) {
            const int p4 = idx & 7;                  // float4 index along p
            const int cl = idx >> 3;                 // 0..127
            const float4 v = *(const float4*)&x[((size_t)(b * C_ + c0 + cl)) * STRIDE_T
                                                + HW_ + p0 + 4 * p4];
            tile[4 * p4 + 0][cl] = v.x;
            tile[4 * p4 + 1][cl] = v.y;
            tile[4 * p4 + 2][cl] = v.z;
            tile[4 * p4 + 3][cl] = v.w;
        }
        __syncthreads();

        // write: warp owns one p row, lanes sweep channels.
        for (int idx = tid; idx < 1024; idx += 384) {
            const int orow_i = idx >> 5;             // 0..31 (constant per warp)
            const int lane   = idx & 31;
            const int pr = p0 + orow_i;
            if (pr < HW_) {
                float* orow = out + ((size_t)b * ROWS_ + 122 + pr) * C_ + c0;
#pragma unroll
                for (int q = 0; q < 4; ++q)
                    orow[lane + 32 * q] = tile[orow_i][lane + 32 * q];
            }
        }
    }
}

// ---------------------------------------------------------------------------
// K2: per-batch reduce (32 chunks, double, fixed order) + bitonic sort of 512
// (value desc, index asc — jax.lax.top_k semantics). Then an O(1) counting
// rank over a 360-bit mask converts the top-120 into a p-ASCENDING list with
// carried ranks: g_topk_sorted[b][pos] = (p<<16)|rank. This makes the gather
// kernel's lane access pattern sequential in p (few L1 lines per warp-LDG).
// Also writes the two cls rows of the output. grid (B), 512 threads.
// ---------------------------------------------------------------------------
__global__ void topk_kernel(const float* __restrict__ cls,
                            float* __restrict__ out) {
    const int b   = blockIdx.x;
    const int tid = threadIdx.x;

    __shared__ double sv[512];
    __shared__ int    si[512];
    __shared__ unsigned pmask[12];       // 384-bit bitmask of selected p's

    double v;
    int    idx = tid;
    if (tid < HW_) {
        const float* gp = (const float*)&g_partial4[b][0][0];
        double s = 0.0;
#pragma unroll 8
        for (int j = 0; j < CHUNKS; ++j) s += (double)gp[j * HW_ + tid];
        v = s;
    } else {
        v = -1e300;
    }
    if (tid < 12) pmask[tid] = 0u;

    for (int k = 2; k <= 512; k <<= 1) {
        const bool up = ((tid & k) == 0);
        int j = k >> 1;
        for (; j >= 32; j >>= 1) {
            sv[tid] = v; si[tid] = idx;
            __syncthreads();
            const double pv = sv[tid ^ j];
            const int    pi = si[tid ^ j];
            __syncthreads();
            const bool iLess = (v > pv) || (v == pv && idx < pi);
            const bool lower = ((tid & j) == 0);
            const bool keepOwn = lower ? (up ? iLess : !iLess)
                                       : (up ? !iLess : iLess);
            if (!keepOwn) { v = pv; idx = pi; }
        }
        for (; j >= 1; j >>= 1) {
            const double pv = __shfl_xor_sync(0xffffffffu, v, j);
            const int    pi = __shfl_xor_sync(0xffffffffu, idx, j);
            const bool iLess = (v > pv) || (v == pv && idx < pi);
            const bool lower = ((tid & j) == 0);
            const bool keepOwn = lower ? (up ? iLess : !iLess)
                                       : (up ? !iLess : iLess);
            if (!keepOwn) { v = pv; idx = pi; }
        }
    }

    // counting rank: sorted position of idx among the selected 120 p's
    if (tid < K_) atomicOr(&pmask[idx >> 5], 1u << (idx & 31));
    __syncthreads();
    if (tid < K_) {
        const int w = idx >> 5;
        int pos = __popc(pmask[w] & ((1u << (idx & 31)) - 1u));
        for (int i = 0; i < w; ++i) pos += __popc(pmask[i]);
        g_topk_sorted[b][pos] = (idx << 16) | tid;   // tid == rank
    }

    // cls rows via float4: row 0 = cls[b,0,:], row 121 = cls[b,1,:]
    {
        const float4* c4 = (const float4*)(cls + (size_t)b * T_ * C_);
        float4* o4 = (float4*)(out + (size_t)b * ROWS_ * C_);
        if (tid < 256)
            o4[tid] = c4[tid];                            // row 0
        else
            o4[(size_t)121 * (C_ / 4) + (tid - 256)] = c4[(C_ / 4) + (tid - 256)]; // row 121
    }
}

// ---------------------------------------------------------------------------
// K3: gather of the 120 selected t=0 tokens, p-SORTED load order.
// grid (16 ctiles of 64 ch, B), block (32,8).
// Lanes carry 32 consecutive p-sorted tokens -> each warp-LDG spans only
// ~3-4 cache lines of one channel row (vs ~28 unsorted). Writes land at the
// original rank's output row (permutation is free for coalesced stores).
// smem pitch 65 -> conflict-free both phases.
// ---------------------------------------------------------------------------
__global__ void gather_kernel(const float* __restrict__ x,
                              float* __restrict__ out) {
    const int c0 = blockIdx.x * 64;
    const int b  = blockIdx.y;
    const int tx = threadIdx.x;          // 0..31
    const int ty = threadIdx.y;          // 0..7
    const int tid = ty * 32 + tx;

    __shared__ float g[120][65];
    __shared__ int   sp[128];            // (p<<16)|rank, ascending p

    for (int i = tid; i < K_; i += 256)
        sp[i] = g_topk_sorted[b][i];
    __syncthreads();

    // load phase: slot groups of 32 along lanes (p ascending), channels on ty
#pragma unroll
    for (int tg = 0; tg < 4; ++tg) {
        const int slot = tg * 32 + tx;
        const bool valid = (slot < K_);
        const int p = valid ? (sp[slot] >> 16) : 0;
#pragma unroll
        for (int cg = 0; cg < 8; ++cg) {
            const int c = ty + 8 * cg;   // 0..63
            if (valid)
                g[slot][c] = x[((size_t)(b * C_ + c0 + c)) * STRIDE_T + p]; // t=0
        }
    }
    __syncthreads();

    // write phase: warp ty owns slots ty, ty+8, ... ; lanes sweep channels;
    // destination row = original rank of that slot.
    for (int slot = ty; slot < K_; slot += 8) {
        const int rank = sp[slot] & 0xffff;
        float* orow = out + ((size_t)b * ROWS_ + 1 + rank) * C_ + c0;
        orow[tx]      = g[slot][tx];
        orow[32 + tx] = g[slot][32 + tx];
    }
}

// ---------------------------------------------------------------------------
extern "C" void kernel_launch(void* const* d_in, const int* in_sizes, int n_in,
                              void* d_out, int out_size) {
    const float* x   = (const float*)d_in[0];
    const float* cls = (const float*)d_in[1];
    // Defensive: x is the huge tensor (94,371,840 elems), cls is 262,144.
    if (n_in >= 2 && in_sizes[0] < in_sizes[1]) {
        const float* tmp = x; x = cls; cls = tmp;
    }
    float* out = (float*)d_out;

    fusedA_kernel <<<dim3(CHUNKS + 96, B_), 384>>>(x, cls, out);
    topk_kernel   <<<B_, 512>>>(cls, out);
    gather_kernel <<<dim3(16, B_), dim3(32, 8)>>>(x, out);
}